// round 15
// baseline (speedup 1.0000x reference)
#include <cuda_runtime.h>
#include <math.h>
#include <stdint.h>

// Problem: B=8, CIN=64, COUT=64, N=16, H=W=32
//
// out[b,o,h,w] = (1/1024)*(T[b,o,hw] + r[b,o]) + conv(v) + conv_b + bias
// gelu Taylor (degree 22, exact to fp32 on |s|<=2.44) + binomial split:
//   gelu(f+g) = sum_{a,bq} d[a][bq] f^a ghat^bq,   ghat = g/1.5
//   d[a][bq]  = c_{a+bq} * C(a+bq,a) * 1.5^bq
// Chain:  v --moments--> M2 --binom T--> F --Q--> H --d--> G --Horner--> out
// All fp32 except d/T coefficient setup (double, computed once).

#define NA 23            // powers 0..22
#define KJ (8*NA)        // 184

// ---- device scratch (static; no allocations) ----
__device__ float g_d[24*24];          // d[a][bq] (zeros outside a+bq<=22)
__device__ float g_T[8*NA*NA];        // [(j*NA+a)*NA + m] binomial*w1 powers
__device__ float g_Q[512*64];         // [(o*8+j)*64 + i]
__device__ float g_s[512];            // [b*64+i]  (spatial sum of v row)
__device__ float g_r[512];            // [b*64+o]
__device__ float g_F[512*KJ];         // [row*KJ + j*NA+a]
__device__ float g_G[512*KJ];         // [(b*64+o)*KJ + j*NA+bq]

// ---------------------------------------------------------------------------
// Setup: d (3 blks), T (17 blks), Q (128 blks).  grid = 148 x 256.
__global__ void k_setup(const float* __restrict__ params,
                        const float* __restrict__ w1,
                        const float* __restrict__ w2) {
    int blk = blockIdx.x, tid = threadIdx.x;
    if (blk < 3) {
        int t = blk*256 + tid;
        if (t < 576) {
            int a = t/24, b = t%24, p = a + b;
            double val = 0.0;
            if (a <= 22 && b <= 22 && p <= 22) {
                double cp = 0.0;
                if (p == 1) cp = 0.5;
                else if (p >= 2 && (p & 1) == 0) {
                    int n = p/2 - 1;
                    double fact = 1.0, pw2 = 1.0;
                    for (int q = 2; q <= n; q++) fact *= q;
                    for (int q = 0; q < n; q++) pw2 *= 2.0;
                    cp = ((n & 1) ? -1.0 : 1.0)
                       / (2.5066282746310002 * fact * (double)(2*n+1) * pw2);
                }
                double C = 1.0;
                for (int q = 1; q <= a; q++) C = C * (double)(p - a + q) / (double)q;
                double gs = 1.0;
                for (int q = 0; q < b; q++) gs *= 1.5;
                val = cp * C * gs;
            }
            g_d[t] = (float)val;
        }
    } else if (blk < 20) {
        int t = (blk-3)*256 + tid;
        if (t < 8*NA*NA) {
            int j = t/(NA*NA), rem = t%(NA*NA), a = rem/NA, m = rem%NA;
            double val = 0.0;
            if (m <= a) {
                double wx = (double)w1[4*j+0], wy = (double)w1[4*j+1];
                double C = 1.0;
                for (int q = 1; q <= m; q++) C = C * (double)(a - m + q) / (double)q;
                double px = 1.0, py = 1.0;
                for (int q = 0; q < m; q++)   px *= wx;
                for (int q = 0; q < a-m; q++) py *= wy;
                val = C * px * py;
            }
            g_T[t] = (float)val;
        }
    } else {
        int idx = (blk-20)*256 + tid;               // < 32768
        int oj = idx >> 6, i = idx & 63;
        int o = oj >> 3, j = oj & 7;
        float acc = 0.f;
#pragma unroll
        for (int n = 0; n < 16; n++)
            acc += __ldg(&w2[n*8+j]) * __ldg(&params[(n*64+o)*64+i]);
        g_Q[idx] = acc;
    }
}

// ---------------------------------------------------------------------------
// Fused per-row pipeline: v row -> M1 -> M2 -> F (+ s).  One CTA per row.
__global__ __launch_bounds__(256) void k_F(const float* __restrict__ v) {
    __shared__ float vsm[32][33];     // [x][y]
    __shared__ float cp [32][24];     // cp[t][m] = c_t^m  (cx grid == cy grid)
    __shared__ float M1s[23][33];     // [my][x]
    __shared__ float M2s[23][24];     // [my][mx]
    __shared__ float Ts [8*NA*NA];

    int row = blockIdx.x;             // 0..511  (b*64+i)
    int tid = threadIdx.x;

    // load v row
    {
        int idx4 = tid * 4;
        int x = idx4 >> 5, y = idx4 & 31;
        float4 f4 = *(const float4*)&v[(size_t)row*1024 + idx4];
        vsm[x][y+0] = f4.x; vsm[x][y+1] = f4.y;
        vsm[x][y+2] = f4.z; vsm[x][y+3] = f4.w;
    }
    // power table
    if (tid < 32) {
        float c = tid*0.0625f - 0.96875f;
        float p = 1.f;
#pragma unroll
        for (int m = 0; m < NA; m++) { cp[tid][m] = p; p *= c; }
    }
    // T coefficients
    for (int idx = tid; idx < 8*NA*NA; idx += 256) Ts[idx] = g_T[idx];
    __syncthreads();

    // M1[my][x] = sum_y vsm[x][y] * cp[y][my]   (736 items)
    for (int item = tid; item < NA*32; item += 256) {
        int my = item >> 5, x = item & 31;
        float acc = 0.f;
#pragma unroll
        for (int y = 0; y < 32; y++) acc += vsm[x][y] * cp[y][my];
        M1s[my][x] = acc;
    }
    __syncthreads();

    // M2[my][mx] = sum_x M1[my][x] * cp[x][mx]  (529 items)
    for (int item = tid; item < NA*NA; item += 256) {
        int my = item / NA, mx = item % NA;
        float acc = 0.f;
#pragma unroll
        for (int x = 0; x < 32; x++) acc += M1s[my][x] * cp[x][mx];
        M2s[my][mx] = acc;
    }
    __syncthreads();

    // F[j*NA+a] = sum_{m<=a} T[j,a,m] * M2[a-m][m]   (184 items)
    if (tid < KJ) {
        int j = tid / NA, a = tid % NA;
        const float* Tr = Ts + (j*NA + a)*NA;
        float acc = 0.f;
        for (int m = 0; m <= a; m++)
            acc += Tr[m] * M2s[a-m][m];
        g_F[(size_t)row*KJ + tid] = acc;
    }
    if (tid == 0) g_s[row] = M2s[0][0];   // spatial sum of v row
}

// ---------------------------------------------------------------------------
// H = Q @ F  then  G = H @ d, one CTA per (b,j).  j==0 CTAs also compute r.
__global__ __launch_bounds__(256) void k_HG(const float* __restrict__ params,
                                            const float* __restrict__ b2) {
    __shared__ float Fs[64][24];      // [i][a]
    __shared__ float Qs[64][64];      // [o][i]
    __shared__ float Hs[64][24];      // [o][a]
    __shared__ float ds[24*24];
    __shared__ float rs[4][64];

    int blk = blockIdx.x;             // 0..63
    int b = blk >> 3, j = blk & 7;
    int tid = threadIdx.x;

    for (int idx = tid; idx < 64*NA; idx += 256) {
        int i = idx / NA, a = idx % NA;
        Fs[i][a] = g_F[(size_t)(b*64+i)*KJ + j*NA + a];
    }
    for (int idx = tid; idx < 4096; idx += 256) {
        int o = idx >> 6, i = idx & 63;
        Qs[o][i] = g_Q[(o*8+j)*64 + i];
    }
    for (int idx = tid; idx < 576; idx += 256) ds[idx] = g_d[idx];
    __syncthreads();

    // H[o][a] = sum_i Qs[o][i]*Fs[i][a]   (1472 items)
    for (int item = tid; item < 64*NA; item += 256) {
        int o = item / NA, a = item % NA;
        float acc = 0.f;
#pragma unroll 16
        for (int i = 0; i < 64; i++) acc += Qs[o][i] * Fs[i][a];
        Hs[o][a] = acc;
    }
    __syncthreads();

    // G[o][bq] = sum_a Hs[o][a]*d[a][bq]  (1472 items)
    for (int item = tid; item < 64*NA; item += 256) {
        int o = item / NA, bq = item % NA;
        float acc = 0.f;
#pragma unroll
        for (int a = 0; a < NA; a++) acc += Hs[o][a] * ds[a*24 + bq];
        g_G[(size_t)(b*64+o)*KJ + j*NA + bq] = acc;
    }

    // r[b,o] = sum_i (sum_n b2[n]*params[n,o,i]) * s[b,i]   (j==0 blocks)
    if (j == 0) {
        int o = tid & 63, part = tid >> 6;
        float acc = 0.f;
        for (int iq = 0; iq < 16; iq++) {
            int i = part*16 + iq;
            float pp = 0.f;
#pragma unroll
            for (int n = 0; n < 16; n++)
                pp += __ldg(&b2[n]) * __ldg(&params[(n*64+o)*64+i]);
            acc += pp * g_s[b*64+i];
        }
        rs[part][o] = acc;
        __syncthreads();
        if (tid < 64)
            g_r[b*64+tid] = rs[0][tid] + rs[1][tid] + rs[2][tid] + rs[3][tid];
    }
}

// ---------------------------------------------------------------------------
// Final output: Horner-evaluated basis GEMM + conv + biases.
// grid = 128 (b8 x og4 x hb4), 256 threads; each thread: 4 o x 4 hw.
__global__ __launch_bounds__(256) void k_out(const float* __restrict__ v,
                                             const float* __restrict__ conv_w,
                                             const float* __restrict__ conv_b,
                                             const float* __restrict__ bias,
                                             const float* __restrict__ w1,
                                             const float* __restrict__ b1,
                                             float* __restrict__ out) {
    __shared__ float Gs[16*KJ];       // 16 o rows x 184
    __shared__ float cws[16*64];
    __shared__ float w1s[32];         // w1(8x4) | b1(8) packed: [0..31]=w1,[32..39]... use 48
    __shared__ float b1s[8];

    int bx = blockIdx.x;
    int b  = bx >> 4;
    int o0 = ((bx >> 2) & 3) * 16;
    int hw0 = (bx & 3) * 256;
    int tid = threadIdx.x;
    int grp = tid >> 6;               // 0..3 -> o quad
    int lx  = tid & 63;
    int c0  = hw0 + lx*4;

    for (int idx = tid; idx < 16*KJ; idx += 256)
        Gs[idx] = g_G[(size_t)(b*64 + o0 + idx/KJ)*KJ + idx%KJ];
    for (int idx = tid; idx < 16*64; idx += 256)
        cws[idx] = conv_w[(o0 + (idx >> 6))*64 + (idx & 63)];
    if (tid < 32) w1s[tid] = w1[tid];
    if (tid < 8)  b1s[tid] = b1[tid];
    __syncthreads();

    float ch  = (c0 >> 5) * 0.0625f - 0.96875f;     // same h for the 4 cols
    float cw0 = (c0 & 31) * 0.0625f - 0.96875f;

    float accA[4][4] = {};
    const float* Gq = Gs + grp*4*KJ;
#pragma unroll
    for (int j = 0; j < 8; j++) {
        float gb = w1s[4*j+2]*ch + b1s[j];
        float ww = w1s[4*j+3];
        float gh0 = (gb + ww*cw0)              * (1.0f/1.5f);
        float gh1 = (gb + ww*(cw0+0.0625f))    * (1.0f/1.5f);
        float gh2 = (gb + ww*(cw0+0.125f))     * (1.0f/1.5f);
        float gh3 = (gb + ww*(cw0+0.1875f))    * (1.0f/1.5f);
        const float* Gj = Gq + j*NA;
#pragma unroll
        for (int o = 0; o < 4; o++) {
            const float* Gc = Gj + o*KJ;
            float h0 = Gc[NA-1], h1 = h0, h2 = h0, h3 = h0;
#pragma unroll
            for (int t = NA-2; t >= 0; t--) {
                float gc = Gc[t];
                h0 = h0*gh0 + gc;
                h1 = h1*gh1 + gc;
                h2 = h2*gh2 + gc;
                h3 = h3*gh3 + gc;
            }
            accA[o][0] += h0; accA[o][1] += h1;
            accA[o][2] += h2; accA[o][3] += h3;
        }
    }

    float accB[4][4] = {};
    const float* cwq = cws + grp*4*64;
#pragma unroll 2
    for (int i = 0; i < 64; i++) {
        float4 vv = *(const float4*)&v[(size_t)(b*64+i)*1024 + c0];
#pragma unroll
        for (int o = 0; o < 4; o++) {
            float cw = cwq[o*64 + i];
            accB[o][0] += cw*vv.x; accB[o][1] += cw*vv.y;
            accB[o][2] += cw*vv.z; accB[o][3] += cw*vv.w;
        }
    }

    const float inv = 1.0f/1024.0f;
#pragma unroll
    for (int o = 0; o < 4; o++) {
        int oo = o0 + grp*4 + o;
        float base = __ldg(&conv_b[oo]) + __ldg(&bias[oo]) + g_r[b*64+oo]*inv;
        float4 res;
        res.x = accA[o][0]*inv + accB[o][0] + base;
        res.y = accA[o][1]*inv + accB[o][1] + base;
        res.z = accA[o][2]*inv + accB[o][2] + base;
        res.w = accA[o][3]*inv + accB[o][3] + base;
        *(float4*)&out[(size_t)(b*64+oo)*1024 + c0] = res;
    }
}

// ---------------------------------------------------------------------------
extern "C" void kernel_launch(void* const* d_in, const int* in_sizes, int n_in,
                              void* d_out, int out_size) {
    const float* v      = (const float*)d_in[0];  // (8,64,32,32)
    const float* params = (const float*)d_in[1];  // (16,64,64)
    const float* w1     = (const float*)d_in[2];  // (8,4)
    const float* b1     = (const float*)d_in[3];  // (8)
    const float* w2     = (const float*)d_in[4];  // (16,8)
    const float* b2     = (const float*)d_in[5];  // (16)
    const float* conv_w = (const float*)d_in[6];  // (64,64)
    const float* conv_b = (const float*)d_in[7];  // (64)
    const float* bias   = (const float*)d_in[8];  // (64,1,1)
    float* out = (float*)d_out;                   // (8,64,32,32)

    k_setup<<<148, 256>>>(params, w1, w2);
    k_F    <<<512, 256>>>(v);
    k_HG   <<<64, 256>>>(params, b2);
    k_out  <<<128, 256>>>(v, conv_w, conv_b, bias, w1, b1, out);
}

// round 16
// speedup vs baseline: 1.0070x; 1.0070x over previous
#include <cuda_runtime.h>
#include <math.h>
#include <stdint.h>

// Problem: B=8, CIN=64, COUT=64, N=16, H=W=32
//
// out[b,o,h,w] = (1/1024)*(T[b,o,hw] + r[b,o]) + conv(v) + conv_b + bias
// gelu Taylor (degree 22, exact to fp32 on |s|<=2.44) + binomial split:
//   gelu(f+g) = sum_{a,bq} d[a][bq] f^a ghat^bq,   ghat = g/1.5
//   d[a][bq]  = c_{a+bq} * C(a+bq,a) * 1.5^bq
// Chain:  v --moments--> M2 --binom T--> F --Q--> H --d--> G --Horner--> out
// All fp32 except d/T coefficient setup (double, computed once).

#define NA 23            // powers 0..22
#define KJ (8*NA)        // 184

// ---- device scratch (static; no allocations) ----
__device__ float g_d[24*24];          // d[a][bq] (zeros outside a+bq<=22)
__device__ float g_T[8*NA*NA];        // [(j*NA+a)*NA + m] binomial*w1 powers
__device__ float g_Q[512*64];         // [(o*8+j)*64 + i]
__device__ float g_s[512];            // [b*64+i]  (spatial sum of v row)
__device__ float g_r[512];            // [b*64+o]
__device__ float g_F[512*KJ];         // [row*KJ + j*NA+a]
__device__ float g_G[512*KJ];         // [(b*64+o)*KJ + j*NA+bq]

// ---------------------------------------------------------------------------
// Setup: d (3 blks), T (17 blks), Q (128 blks).  grid = 148 x 256.
__global__ void k_setup(const float* __restrict__ params,
                        const float* __restrict__ w1,
                        const float* __restrict__ w2) {
    int blk = blockIdx.x, tid = threadIdx.x;
    if (blk < 3) {
        int t = blk*256 + tid;
        if (t < 576) {
            int a = t/24, b = t%24, p = a + b;
            double val = 0.0;
            if (a <= 22 && b <= 22 && p <= 22) {
                double cp = 0.0;
                if (p == 1) cp = 0.5;
                else if (p >= 2 && (p & 1) == 0) {
                    int n = p/2 - 1;
                    double fact = 1.0, pw2 = 1.0;
                    for (int q = 2; q <= n; q++) fact *= q;
                    for (int q = 0; q < n; q++) pw2 *= 2.0;
                    cp = ((n & 1) ? -1.0 : 1.0)
                       / (2.5066282746310002 * fact * (double)(2*n+1) * pw2);
                }
                double C = 1.0;
                for (int q = 1; q <= a; q++) C = C * (double)(p - a + q) / (double)q;
                double gs = 1.0;
                for (int q = 0; q < b; q++) gs *= 1.5;
                val = cp * C * gs;
            }
            g_d[t] = (float)val;
        }
    } else if (blk < 20) {
        int t = (blk-3)*256 + tid;
        if (t < 8*NA*NA) {
            int j = t/(NA*NA), rem = t%(NA*NA), a = rem/NA, m = rem%NA;
            double val = 0.0;
            if (m <= a) {
                double wx = (double)w1[4*j+0], wy = (double)w1[4*j+1];
                double C = 1.0;
                for (int q = 1; q <= m; q++) C = C * (double)(a - m + q) / (double)q;
                double px = 1.0, py = 1.0;
                for (int q = 0; q < m; q++)   px *= wx;
                for (int q = 0; q < a-m; q++) py *= wy;
                val = C * px * py;
            }
            g_T[t] = (float)val;
        }
    } else {
        int idx = (blk-20)*256 + tid;               // < 32768
        int oj = idx >> 6, i = idx & 63;
        int o = oj >> 3, j = oj & 7;
        float acc = 0.f;
#pragma unroll
        for (int n = 0; n < 16; n++)
            acc += __ldg(&w2[n*8+j]) * __ldg(&params[(n*64+o)*64+i]);
        g_Q[idx] = acc;
    }
}

// ---------------------------------------------------------------------------
// Fused per-row pipeline: v row -> M1 -> M2 -> F (+ s).  One CTA per row.
__global__ __launch_bounds__(256) void k_F(const float* __restrict__ v) {
    __shared__ float vsm[32][33];     // [x][y]
    __shared__ float cp [32][24];     // cp[t][m] = c_t^m  (cx grid == cy grid)
    __shared__ float M1s[23][33];     // [my][x]
    __shared__ float M2s[23][24];     // [my][mx]
    __shared__ float Ts [8*NA*NA];

    int row = blockIdx.x;             // 0..511  (b*64+i)
    int tid = threadIdx.x;

    // load v row
    {
        int idx4 = tid * 4;
        int x = idx4 >> 5, y = idx4 & 31;
        float4 f4 = *(const float4*)&v[(size_t)row*1024 + idx4];
        vsm[x][y+0] = f4.x; vsm[x][y+1] = f4.y;
        vsm[x][y+2] = f4.z; vsm[x][y+3] = f4.w;
    }
    // power table
    if (tid < 32) {
        float c = tid*0.0625f - 0.96875f;
        float p = 1.f;
#pragma unroll
        for (int m = 0; m < NA; m++) { cp[tid][m] = p; p *= c; }
    }
    // T coefficients
    for (int idx = tid; idx < 8*NA*NA; idx += 256) Ts[idx] = g_T[idx];
    __syncthreads();

    // M1[my][x] = sum_y vsm[x][y] * cp[y][my]   (736 items)
    for (int item = tid; item < NA*32; item += 256) {
        int my = item >> 5, x = item & 31;
        float acc = 0.f;
#pragma unroll
        for (int y = 0; y < 32; y++) acc += vsm[x][y] * cp[y][my];
        M1s[my][x] = acc;
    }
    __syncthreads();

    // M2[my][mx] = sum_x M1[my][x] * cp[x][mx]  (529 items)
    for (int item = tid; item < NA*NA; item += 256) {
        int my = item / NA, mx = item % NA;
        float acc = 0.f;
#pragma unroll
        for (int x = 0; x < 32; x++) acc += M1s[my][x] * cp[x][mx];
        M2s[my][mx] = acc;
    }
    __syncthreads();

    // F[j*NA+a] = sum_{m<=a} T[j,a,m] * M2[a-m][m]   (184 items)
    if (tid < KJ) {
        int j = tid / NA, a = tid % NA;
        const float* Tr = Ts + (j*NA + a)*NA;
        float acc = 0.f;
        for (int m = 0; m <= a; m++)
            acc += Tr[m] * M2s[a-m][m];
        g_F[(size_t)row*KJ + tid] = acc;
    }
    if (tid == 0) g_s[row] = M2s[0][0];   // spatial sum of v row
}

// ---------------------------------------------------------------------------
// H = Q @ F  then  G = H @ d, one CTA per (b,j).  j==0 CTAs also compute r.
__global__ __launch_bounds__(256) void k_HG(const float* __restrict__ params,
                                            const float* __restrict__ b2) {
    __shared__ float Fs[64][24];      // [i][a]
    __shared__ float Qs[64][64];      // [o][i]
    __shared__ float Hs[64][24];      // [o][a]
    __shared__ float ds[24*24];
    __shared__ float rs[4][64];

    int blk = blockIdx.x;             // 0..63
    int b = blk >> 3, j = blk & 7;
    int tid = threadIdx.x;

    for (int idx = tid; idx < 64*NA; idx += 256) {
        int i = idx / NA, a = idx % NA;
        Fs[i][a] = g_F[(size_t)(b*64+i)*KJ + j*NA + a];
    }
    for (int idx = tid; idx < 4096; idx += 256) {
        int o = idx >> 6, i = idx & 63;
        Qs[o][i] = g_Q[(o*8+j)*64 + i];
    }
    for (int idx = tid; idx < 576; idx += 256) ds[idx] = g_d[idx];
    __syncthreads();

    // H[o][a] = sum_i Qs[o][i]*Fs[i][a]   (1472 items)
    for (int item = tid; item < 64*NA; item += 256) {
        int o = item / NA, a = item % NA;
        float acc = 0.f;
#pragma unroll 16
        for (int i = 0; i < 64; i++) acc += Qs[o][i] * Fs[i][a];
        Hs[o][a] = acc;
    }
    __syncthreads();

    // G[o][bq] = sum_a Hs[o][a]*d[a][bq]  (1472 items)
    for (int item = tid; item < 64*NA; item += 256) {
        int o = item / NA, bq = item % NA;
        float acc = 0.f;
#pragma unroll
        for (int a = 0; a < NA; a++) acc += Hs[o][a] * ds[a*24 + bq];
        g_G[(size_t)(b*64+o)*KJ + j*NA + bq] = acc;
    }

    // r[b,o] = sum_i (sum_n b2[n]*params[n,o,i]) * s[b,i]   (j==0 blocks)
    if (j == 0) {
        int o = tid & 63, part = tid >> 6;
        float acc = 0.f;
        for (int iq = 0; iq < 16; iq++) {
            int i = part*16 + iq;
            float pp = 0.f;
#pragma unroll
            for (int n = 0; n < 16; n++)
                pp += __ldg(&b2[n]) * __ldg(&params[(n*64+o)*64+i]);
            acc += pp * g_s[b*64+i];
        }
        rs[part][o] = acc;
        __syncthreads();
        if (tid < 64)
            g_r[b*64+tid] = rs[0][tid] + rs[1][tid] + rs[2][tid] + rs[3][tid];
    }
}

// ---------------------------------------------------------------------------
// Final output: Horner-evaluated basis GEMM + conv + biases.
// grid = 128 (b8 x og4 x hb4), 256 threads; each thread: 4 o x 4 hw.
__global__ __launch_bounds__(256) void k_out(const float* __restrict__ v,
                                             const float* __restrict__ conv_w,
                                             const float* __restrict__ conv_b,
                                             const float* __restrict__ bias,
                                             const float* __restrict__ w1,
                                             const float* __restrict__ b1,
                                             float* __restrict__ out) {
    __shared__ float Gs[16*KJ];       // 16 o rows x 184
    __shared__ float cws[16*64];
    __shared__ float w1s[32];         // w1(8x4) | b1(8) packed: [0..31]=w1,[32..39]... use 48
    __shared__ float b1s[8];

    int bx = blockIdx.x;
    int b  = bx >> 4;
    int o0 = ((bx >> 2) & 3) * 16;
    int hw0 = (bx & 3) * 256;
    int tid = threadIdx.x;
    int grp = tid >> 6;               // 0..3 -> o quad
    int lx  = tid & 63;
    int c0  = hw0 + lx*4;

    for (int idx = tid; idx < 16*KJ; idx += 256)
        Gs[idx] = g_G[(size_t)(b*64 + o0 + idx/KJ)*KJ + idx%KJ];
    for (int idx = tid; idx < 16*64; idx += 256)
        cws[idx] = conv_w[(o0 + (idx >> 6))*64 + (idx & 63)];
    if (tid < 32) w1s[tid] = w1[tid];
    if (tid < 8)  b1s[tid] = b1[tid];
    __syncthreads();

    float ch  = (c0 >> 5) * 0.0625f - 0.96875f;     // same h for the 4 cols
    float cw0 = (c0 & 31) * 0.0625f - 0.96875f;

    float accA[4][4] = {};
    const float* Gq = Gs + grp*4*KJ;
#pragma unroll
    for (int j = 0; j < 8; j++) {
        float gb = w1s[4*j+2]*ch + b1s[j];
        float ww = w1s[4*j+3];
        float gh0 = (gb + ww*cw0)              * (1.0f/1.5f);
        float gh1 = (gb + ww*(cw0+0.0625f))    * (1.0f/1.5f);
        float gh2 = (gb + ww*(cw0+0.125f))     * (1.0f/1.5f);
        float gh3 = (gb + ww*(cw0+0.1875f))    * (1.0f/1.5f);
        const float* Gj = Gq + j*NA;
#pragma unroll
        for (int o = 0; o < 4; o++) {
            const float* Gc = Gj + o*KJ;
            float h0 = Gc[NA-1], h1 = h0, h2 = h0, h3 = h0;
#pragma unroll
            for (int t = NA-2; t >= 0; t--) {
                float gc = Gc[t];
                h0 = h0*gh0 + gc;
                h1 = h1*gh1 + gc;
                h2 = h2*gh2 + gc;
                h3 = h3*gh3 + gc;
            }
            accA[o][0] += h0; accA[o][1] += h1;
            accA[o][2] += h2; accA[o][3] += h3;
        }
    }

    float accB[4][4] = {};
    const float* cwq = cws + grp*4*64;
#pragma unroll 2
    for (int i = 0; i < 64; i++) {
        float4 vv = *(const float4*)&v[(size_t)(b*64+i)*1024 + c0];
#pragma unroll
        for (int o = 0; o < 4; o++) {
            float cw = cwq[o*64 + i];
            accB[o][0] += cw*vv.x; accB[o][1] += cw*vv.y;
            accB[o][2] += cw*vv.z; accB[o][3] += cw*vv.w;
        }
    }

    const float inv = 1.0f/1024.0f;
#pragma unroll
    for (int o = 0; o < 4; o++) {
        int oo = o0 + grp*4 + o;
        float base = __ldg(&conv_b[oo]) + __ldg(&bias[oo]) + g_r[b*64+oo]*inv;
        float4 res;
        res.x = accA[o][0]*inv + accB[o][0] + base;
        res.y = accA[o][1]*inv + accB[o][1] + base;
        res.z = accA[o][2]*inv + accB[o][2] + base;
        res.w = accA[o][3]*inv + accB[o][3] + base;
        *(float4*)&out[(size_t)(b*64+oo)*1024 + c0] = res;
    }
}

// ---------------------------------------------------------------------------
extern "C" void kernel_launch(void* const* d_in, const int* in_sizes, int n_in,
                              void* d_out, int out_size) {
    const float* v      = (const float*)d_in[0];  // (8,64,32,32)
    const float* params = (const float*)d_in[1];  // (16,64,64)
    const float* w1     = (const float*)d_in[2];  // (8,4)
    const float* b1     = (const float*)d_in[3];  // (8)
    const float* w2     = (const float*)d_in[4];  // (16,8)
    const float* b2     = (const float*)d_in[5];  // (16)
    const float* conv_w = (const float*)d_in[6];  // (64,64)
    const float* conv_b = (const float*)d_in[7];  // (64)
    const float* bias   = (const float*)d_in[8];  // (64,1,1)
    float* out = (float*)d_out;                   // (8,64,32,32)

    k_setup<<<148, 256>>>(params, w1, w2);
    k_F    <<<512, 256>>>(v);
    k_HG   <<<64, 256>>>(params, b2);
    k_out  <<<128, 256>>>(v, conv_w, conv_b, bias, w1, b1, out);
}